// round 11
// baseline (speedup 1.0000x reference)
#include <cuda_runtime.h>
#include <cuda_bf16.h>
#include <cstdint>

#define N_NODES 50000
#define N_EDGES 800000
#define FEAT    64
#define CAP     128

__device__ int g_cnt[N_NODES];
__device__ int g_slot[(size_t)N_NODES * CAP];

// ---- packed fp32x2 helpers (sm_103a native) --------------------------------
__device__ __forceinline__ unsigned long long f2pk(float x, float y) {
    unsigned long long r;
    asm("mov.b64 %0, {%1, %2};" : "=l"(r) : "f"(x), "f"(y));
    return r;
}
__device__ __forceinline__ unsigned long long f2add(unsigned long long a,
                                                    unsigned long long b) {
    unsigned long long r;
    asm("add.rn.f32x2 %0, %1, %2;" : "=l"(r) : "l"(a), "l"(b));
    return r;
}
__device__ __forceinline__ float2 f2upk(unsigned long long v) {
    float2 r;
    asm("mov.b64 {%0, %1}, %2;" : "=f"(r.x), "=f"(r.y) : "l"(v));
    return r;
}

// ---------------------------------------------------------------------------
// Pass 1: bucket build. One thread per 4 edges (int4 loads).
// ---------------------------------------------------------------------------
__global__ void build_buckets_kernel(const int4* __restrict__ es4,
                                     const int4* __restrict__ ed4,
                                     int*        __restrict__ cnt,
                                     int*        __restrict__ slot)
{
    int t = blockIdx.x * blockDim.x + threadIdx.x;
    if (t >= N_EDGES / 4) return;
    int4 s = __ldg(es4 + t);
    int4 d = __ldg(ed4 + t);
    int p;
    p = atomicAdd(cnt + d.x, 1); if (p < CAP) slot[(size_t)d.x * CAP + p] = s.x;
    p = atomicAdd(cnt + d.y, 1); if (p < CAP) slot[(size_t)d.y * CAP + p] = s.y;
    p = atomicAdd(cnt + d.z, 1); if (p < CAP) slot[(size_t)d.z * CAP + p] = s.z;
    p = atomicAdd(cnt + d.w, 1); if (p < CAP) slot[(size_t)d.w * CAP + p] = s.w;
}

// ---------------------------------------------------------------------------
// Pass 2 (fused): R10 structure (smem-staged indices, warp-local sync),
// with two instruction-stream reductions:
//   - slot indices read via LDS.128 (2 per 8-batch instead of 8 LDS.32)
//   - accumulation in packed add.rn.f32x2 (16 ops/batch instead of 32 FADD)
// NO launch_bounds: the 8 in-flight float4 gathers need ~38 regs (R7 lesson).
// ---------------------------------------------------------------------------
#define NODES_PER_BLOCK 16   // 256 threads; 50000/16 = 3125 exact blocks

__global__ void
gather_matmul_kernel(const float4* __restrict__ src4,
                     const float4* __restrict__ dst4,
                     const int*    __restrict__ cnt,
                     const int*    __restrict__ slot,
                     float*        __restrict__ out)
{
    __shared__ float  S_sm[NODES_PER_BLOCK][68];              // padded rows
    __shared__ float4 D_sm[NODES_PER_BLOCK][18];
    __shared__ alignas(16) int slot_sm[NODES_PER_BLOCK][32];  // int4-aligned

    int local = threadIdx.x >> 4;
    int c     = threadIdx.x & 15;
    int n     = blockIdx.x * NODES_PER_BLOCK + local;   // exact grid

    int k = __ldg(cnt + n);    // overlaps the staging load below

    // Stage first 32 slot indices (one int2/thread, coalesced 128B/node).
    // Entries beyond cnt[n] are stale-but-valid ids, never accumulated.
    {
        int2 v = __ldg(reinterpret_cast<const int2*>(slot + (size_t)n * CAP) + c);
        slot_sm[local][c * 2]     = v.x;
        slot_sm[local][c * 2 + 1] = v.y;
    }
    __syncwarp();

    if (k > CAP) k = CAP;
    int kc = k < 32 ? k : 32;

    const int4* slv = reinterpret_cast<const int4*>(slot_sm[local]);

    unsigned long long axy = 0ull, azw = 0ull;   // packed (0.f,0.f)

    int j = 0;
    for (; j + 8 <= kc; j += 8) {
        int4 sa = slv[j >> 2];          // LDS.128 (broadcast in half-warp)
        int4 sb = slv[(j >> 2) + 1];
        float4 v0 = __ldg(src4 + (size_t)sa.x * 16 + c);
        float4 v1 = __ldg(src4 + (size_t)sa.y * 16 + c);
        float4 v2 = __ldg(src4 + (size_t)sa.z * 16 + c);
        float4 v3 = __ldg(src4 + (size_t)sa.w * 16 + c);
        float4 v4 = __ldg(src4 + (size_t)sb.x * 16 + c);
        float4 v5 = __ldg(src4 + (size_t)sb.y * 16 + c);
        float4 v6 = __ldg(src4 + (size_t)sb.z * 16 + c);
        float4 v7 = __ldg(src4 + (size_t)sb.w * 16 + c);
        // packed pairwise tree: 8 f32x2 adds per half (16 total vs 32 FADD)
        unsigned long long t0, t1, t2, t3;
        t0 = f2add(f2pk(v0.x, v0.y), f2pk(v1.x, v1.y));
        t1 = f2add(f2pk(v2.x, v2.y), f2pk(v3.x, v3.y));
        t2 = f2add(f2pk(v4.x, v4.y), f2pk(v5.x, v5.y));
        t3 = f2add(f2pk(v6.x, v6.y), f2pk(v7.x, v7.y));
        t0 = f2add(t0, t1); t2 = f2add(t2, t3);
        axy = f2add(axy, f2add(t0, t2));
        t0 = f2add(f2pk(v0.z, v0.w), f2pk(v1.z, v1.w));
        t1 = f2add(f2pk(v2.z, v2.w), f2pk(v3.z, v3.w));
        t2 = f2add(f2pk(v4.z, v4.w), f2pk(v5.z, v5.w));
        t3 = f2add(f2pk(v6.z, v6.w), f2pk(v7.z, v7.w));
        t0 = f2add(t0, t1); t2 = f2add(t2, t3);
        azw = f2add(azw, f2add(t0, t2));
    }
    if (j + 4 <= kc) {
        int4 sa = slv[j >> 2];
        float4 v0 = __ldg(src4 + (size_t)sa.x * 16 + c);
        float4 v1 = __ldg(src4 + (size_t)sa.y * 16 + c);
        float4 v2 = __ldg(src4 + (size_t)sa.z * 16 + c);
        float4 v3 = __ldg(src4 + (size_t)sa.w * 16 + c);
        unsigned long long t0, t1;
        t0 = f2add(f2pk(v0.x, v0.y), f2pk(v1.x, v1.y));
        t1 = f2add(f2pk(v2.x, v2.y), f2pk(v3.x, v3.y));
        axy = f2add(axy, f2add(t0, t1));
        t0 = f2add(f2pk(v0.z, v0.w), f2pk(v1.z, v1.w));
        t1 = f2add(f2pk(v2.z, v2.w), f2pk(v3.z, v3.w));
        azw = f2add(azw, f2add(t0, t1));
        j += 4;
    }
    for (; j < kc; ++j) {
        int s = slot_sm[local][j];
        float4 v = __ldg(src4 + (size_t)s * 16 + c);
        axy = f2add(axy, f2pk(v.x, v.y));
        azw = f2add(azw, f2pk(v.z, v.w));
    }
    // Rare fallback: degree > 32 — global slot reads.
    for (j = 32; j < k; ++j) {
        int s = __ldg(slot + (size_t)n * CAP + j);
        float4 v = __ldg(src4 + (size_t)s * 16 + c);
        axy = f2add(axy, f2pk(v.x, v.y));
        azw = f2add(azw, f2pk(v.z, v.w));
    }

    {
        float2 lo = f2upk(axy);
        float2 hi = f2upk(azw);
        *reinterpret_cast<float4*>(&S_sm[local][c * 4]) =
            make_float4(lo.x, lo.y, hi.x, hi.y);
    }
    D_sm[local][c] = __ldg(dst4 + (size_t)n * 16 + c);
    __syncwarp();

    {
        int i  = c >> 1;
        int jh = c & 1;
        float4 o = make_float4(0.f, 0.f, 0.f, 0.f);
        #pragma unroll
        for (int p = 0; p < 8; ++p) {
            float  a = S_sm[local][i * 8 + p];
            float4 b = D_sm[local][p * 2 + jh];
            o.x = fmaf(a, b.x, o.x);
            o.y = fmaf(a, b.y, o.y);
            o.z = fmaf(a, b.z, o.z);
            o.w = fmaf(a, b.w, o.w);
        }
        const float inv = 0.3535533905932737622f;   // 1/sqrt(8)
        o.x *= inv; o.y *= inv; o.z *= inv; o.w *= inv;
        reinterpret_cast<float4*>(out + (size_t)n * FEAT)[c] = o;
    }
}

extern "C" void kernel_launch(void* const* d_in, const int* in_sizes, int n_in,
                              void* d_out, int out_size)
{
    const float* src_feat = (const float*)d_in[0];
    const float* dst_feat = (const float*)d_in[1];
    const int*   edge_src = (const int*)d_in[2];
    const int*   edge_dst = (const int*)d_in[3];
    float*       out      = (float*)d_out;

    void* cnt_ptr  = nullptr;
    void* slot_ptr = nullptr;
    cudaGetSymbolAddress(&cnt_ptr, g_cnt);
    cudaGetSymbolAddress(&slot_ptr, g_slot);

    cudaMemsetAsync(cnt_ptr, 0, (size_t)N_NODES * sizeof(int), 0);

    {
        int threads = 256;
        int work    = N_EDGES / 4;                 // 200000
        int blocks  = (work + threads - 1) / threads;
        build_buckets_kernel<<<blocks, threads>>>(
            reinterpret_cast<const int4*>(edge_src),
            reinterpret_cast<const int4*>(edge_dst),
            (int*)cnt_ptr, (int*)slot_ptr);
    }
    {
        int threads = NODES_PER_BLOCK * 16;        // 256
        int blocks  = N_NODES / NODES_PER_BLOCK;   // 3125 exact
        gather_matmul_kernel<<<blocks, threads>>>(
            reinterpret_cast<const float4*>(src_feat),
            reinterpret_cast<const float4*>(dst_feat),
            (const int*)cnt_ptr, (const int*)slot_ptr, out);
    }
}

// round 12
// speedup vs baseline: 1.0387x; 1.0387x over previous
#include <cuda_runtime.h>
#include <cuda_bf16.h>
#include <cstdint>

#define N_NODES 50000
#define N_EDGES 800000
#define FEAT    64
#define CAP     64   // Poisson(16) in-degree: P(deg>=64) ~ 2e-18/node; 32<deg<=64 handled by fallback

__device__ int g_cnt[N_NODES];
__device__ int g_slot[(size_t)N_NODES * CAP];

// ---------------------------------------------------------------------------
// Pass 1: bucket build. One thread per 4 edges (int4 loads).
// ---------------------------------------------------------------------------
__global__ void build_buckets_kernel(const int4* __restrict__ es4,
                                     const int4* __restrict__ ed4,
                                     int*        __restrict__ cnt,
                                     int*        __restrict__ slot)
{
    int t = blockIdx.x * blockDim.x + threadIdx.x;
    if (t >= N_EDGES / 4) return;
    int4 s = __ldg(es4 + t);
    int4 d = __ldg(ed4 + t);
    int p;
    p = atomicAdd(cnt + d.x, 1); if (p < CAP) slot[(size_t)d.x * CAP + p] = s.x;
    p = atomicAdd(cnt + d.y, 1); if (p < CAP) slot[(size_t)d.y * CAP + p] = s.y;
    p = atomicAdd(cnt + d.z, 1); if (p < CAP) slot[(size_t)d.z * CAP + p] = s.z;
    p = atomicAdd(cnt + d.w, 1); if (p < CAP) slot[(size_t)d.w * CAP + p] = s.w;
}

// ---------------------------------------------------------------------------
// Pass 2 (fused): R10 gather (proven 22.0us): smem-staged indices, warp-local
// sync, 8-wide float4 gather batches, scalar FADD accumulation.
// NO launch_bounds (needs ~38 regs for 8 in-flight loads; forcing 32 -> 41us).
// ---------------------------------------------------------------------------
#define NODES_PER_BLOCK 16   // 256 threads; 50000/16 = 3125 exact blocks

__global__ void
gather_matmul_kernel(const float4* __restrict__ src4,
                     const float4* __restrict__ dst4,
                     const int*    __restrict__ cnt,
                     const int*    __restrict__ slot,
                     float*        __restrict__ out)
{
    __shared__ float  S_sm[NODES_PER_BLOCK][68];     // padded rows
    __shared__ float4 D_sm[NODES_PER_BLOCK][18];
    __shared__ int    slot_sm[NODES_PER_BLOCK][33];  // 32 idx + pad

    int local = threadIdx.x >> 4;
    int c     = threadIdx.x & 15;
    int n     = blockIdx.x * NODES_PER_BLOCK + local;   // exact grid

    // cnt load issued first — overlaps the staging load below.
    int k = __ldg(cnt + n);

    // Stage first 32 slot indices of this node (one int2/thread, coalesced).
    // Entries beyond cnt[n] are stale-but-valid ids, never accumulated.
    {
        int2 v = __ldg(reinterpret_cast<const int2*>(slot + (size_t)n * CAP) + c);
        slot_sm[local][c * 2]     = v.x;
        slot_sm[local][c * 2 + 1] = v.y;
    }
    __syncwarp();   // producers == consumers' half-warp

    if (k > CAP) k = CAP;
    int kc = k < 32 ? k : 32;

    float4 acc = make_float4(0.f, 0.f, 0.f, 0.f);

    int j = 0;
    // 8-wide unroll: indices from smem (broadcast LDS), 8 independent 256B
    // row gathers in flight per group.
    for (; j + 8 <= kc; j += 8) {
        int s0 = slot_sm[local][j + 0];
        int s1 = slot_sm[local][j + 1];
        int s2 = slot_sm[local][j + 2];
        int s3 = slot_sm[local][j + 3];
        int s4 = slot_sm[local][j + 4];
        int s5 = slot_sm[local][j + 5];
        int s6 = slot_sm[local][j + 6];
        int s7 = slot_sm[local][j + 7];
        float4 v0 = __ldg(src4 + (size_t)s0 * 16 + c);
        float4 v1 = __ldg(src4 + (size_t)s1 * 16 + c);
        float4 v2 = __ldg(src4 + (size_t)s2 * 16 + c);
        float4 v3 = __ldg(src4 + (size_t)s3 * 16 + c);
        float4 v4 = __ldg(src4 + (size_t)s4 * 16 + c);
        float4 v5 = __ldg(src4 + (size_t)s5 * 16 + c);
        float4 v6 = __ldg(src4 + (size_t)s6 * 16 + c);
        float4 v7 = __ldg(src4 + (size_t)s7 * 16 + c);
        acc.x += (v0.x + v1.x) + (v2.x + v3.x) + ((v4.x + v5.x) + (v6.x + v7.x));
        acc.y += (v0.y + v1.y) + (v2.y + v3.y) + ((v4.y + v5.y) + (v6.y + v7.y));
        acc.z += (v0.z + v1.z) + (v2.z + v3.z) + ((v4.z + v5.z) + (v6.z + v7.z));
        acc.w += (v0.w + v1.w) + (v2.w + v3.w) + ((v4.w + v5.w) + (v6.w + v7.w));
    }
    if (j + 4 <= kc) {
        int s0 = slot_sm[local][j + 0];
        int s1 = slot_sm[local][j + 1];
        int s2 = slot_sm[local][j + 2];
        int s3 = slot_sm[local][j + 3];
        float4 v0 = __ldg(src4 + (size_t)s0 * 16 + c);
        float4 v1 = __ldg(src4 + (size_t)s1 * 16 + c);
        float4 v2 = __ldg(src4 + (size_t)s2 * 16 + c);
        float4 v3 = __ldg(src4 + (size_t)s3 * 16 + c);
        acc.x += (v0.x + v1.x) + (v2.x + v3.x);
        acc.y += (v0.y + v1.y) + (v2.y + v3.y);
        acc.z += (v0.z + v1.z) + (v2.z + v3.z);
        acc.w += (v0.w + v1.w) + (v2.w + v3.w);
        j += 4;
    }
    for (; j < kc; ++j) {
        int s = slot_sm[local][j];
        float4 v = __ldg(src4 + (size_t)s * 16 + c);
        acc.x += v.x; acc.y += v.y; acc.z += v.z; acc.w += v.w;
    }
    // Rare fallback: degree > 32 — global slot reads.
    for (j = 32; j < k; ++j) {
        int s = __ldg(slot + (size_t)n * CAP + j);
        float4 v = __ldg(src4 + (size_t)s * 16 + c);
        acc.x += v.x; acc.y += v.y; acc.z += v.z; acc.w += v.w;
    }

    *reinterpret_cast<float4*>(&S_sm[local][c * 4]) = acc;
    D_sm[local][c] = __ldg(dst4 + (size_t)n * 16 + c);
    __syncwarp();   // same half-warp produces and consumes S_sm/D_sm rows

    {
        int i  = c >> 1;
        int jh = c & 1;
        float4 o = make_float4(0.f, 0.f, 0.f, 0.f);
        #pragma unroll
        for (int p = 0; p < 8; ++p) {
            float  a = S_sm[local][i * 8 + p];
            float4 b = D_sm[local][p * 2 + jh];
            o.x = fmaf(a, b.x, o.x);
            o.y = fmaf(a, b.y, o.y);
            o.z = fmaf(a, b.z, o.z);
            o.w = fmaf(a, b.w, o.w);
        }
        const float inv = 0.3535533905932737622f;   // 1/sqrt(8)
        o.x *= inv; o.y *= inv; o.z *= inv; o.w *= inv;
        reinterpret_cast<float4*>(out + (size_t)n * FEAT)[c] = o;
    }
}

extern "C" void kernel_launch(void* const* d_in, const int* in_sizes, int n_in,
                              void* d_out, int out_size)
{
    const float* src_feat = (const float*)d_in[0];
    const float* dst_feat = (const float*)d_in[1];
    const int*   edge_src = (const int*)d_in[2];
    const int*   edge_dst = (const int*)d_in[3];
    float*       out      = (float*)d_out;

    void* cnt_ptr  = nullptr;
    void* slot_ptr = nullptr;
    cudaGetSymbolAddress(&cnt_ptr, g_cnt);
    cudaGetSymbolAddress(&slot_ptr, g_slot);

    cudaMemsetAsync(cnt_ptr, 0, (size_t)N_NODES * sizeof(int), 0);

    {
        int threads = 256;
        int work    = N_EDGES / 4;                 // 200000
        int blocks  = (work + threads - 1) / threads;
        build_buckets_kernel<<<blocks, threads>>>(
            reinterpret_cast<const int4*>(edge_src),
            reinterpret_cast<const int4*>(edge_dst),
            (int*)cnt_ptr, (int*)slot_ptr);
    }
    {
        int threads = NODES_PER_BLOCK * 16;        // 256
        int blocks  = N_NODES / NODES_PER_BLOCK;   // 3125 exact
        gather_matmul_kernel<<<blocks, threads>>>(
            reinterpret_cast<const float4*>(src_feat),
            reinterpret_cast<const float4*>(dst_feat),
            (const int*)cnt_ptr, (const int*)slot_ptr, out);
    }
}

// round 13
// speedup vs baseline: 1.0462x; 1.0073x over previous
#include <cuda_runtime.h>
#include <cuda_bf16.h>
#include <cstdint>

#define N_NODES 50000
#define N_EDGES 800000
#define FEAT    64
#define CAP     64   // Poisson(16) in-degree: P(deg>=64) ~ 2e-18/node; 32<deg<=64 via fallback

__device__ int g_cnt[N_NODES];
__device__ int g_slot[(size_t)N_NODES * CAP];

// ---------------------------------------------------------------------------
// Pass 1: bucket build. One thread per 8 edges (2x int4 loads) -> 8
// independent atomic+store chains per thread (R10-measured best).
// ---------------------------------------------------------------------------
__global__ void build_buckets_kernel(const int4* __restrict__ es4,
                                     const int4* __restrict__ ed4,
                                     int*        __restrict__ cnt,
                                     int*        __restrict__ slot)
{
    int t = blockIdx.x * blockDim.x + threadIdx.x;
    if (t >= N_EDGES / 8) return;
    int4 s0 = __ldg(es4 + 2 * t);
    int4 s1 = __ldg(es4 + 2 * t + 1);
    int4 d0 = __ldg(ed4 + 2 * t);
    int4 d1 = __ldg(ed4 + 2 * t + 1);
    int p;
    p = atomicAdd(cnt + d0.x, 1); if (p < CAP) slot[(size_t)d0.x * CAP + p] = s0.x;
    p = atomicAdd(cnt + d0.y, 1); if (p < CAP) slot[(size_t)d0.y * CAP + p] = s0.y;
    p = atomicAdd(cnt + d0.z, 1); if (p < CAP) slot[(size_t)d0.z * CAP + p] = s0.z;
    p = atomicAdd(cnt + d0.w, 1); if (p < CAP) slot[(size_t)d0.w * CAP + p] = s0.w;
    p = atomicAdd(cnt + d1.x, 1); if (p < CAP) slot[(size_t)d1.x * CAP + p] = s1.x;
    p = atomicAdd(cnt + d1.y, 1); if (p < CAP) slot[(size_t)d1.y * CAP + p] = s1.y;
    p = atomicAdd(cnt + d1.z, 1); if (p < CAP) slot[(size_t)d1.z * CAP + p] = s1.z;
    p = atomicAdd(cnt + d1.w, 1); if (p < CAP) slot[(size_t)d1.w * CAP + p] = s1.w;
}

// ---------------------------------------------------------------------------
// Pass 2 (fused): R12 gather body (proven), 128-thread blocks (8 nodes) for
// finer scheduling granularity / higher achieved occupancy.
// NO launch_bounds (8 in-flight float4 gathers need ~34-38 regs; R7 lesson).
// ---------------------------------------------------------------------------
#define NODES_PER_BLOCK 8   // 128 threads; 50000/8 = 6250 exact blocks

__global__ void
gather_matmul_kernel(const float4* __restrict__ src4,
                     const float4* __restrict__ dst4,
                     const int*    __restrict__ cnt,
                     const int*    __restrict__ slot,
                     float*        __restrict__ out)
{
    __shared__ float  S_sm[NODES_PER_BLOCK][68];     // padded rows
    __shared__ float4 D_sm[NODES_PER_BLOCK][18];
    __shared__ int    slot_sm[NODES_PER_BLOCK][33];  // 32 idx + pad

    int local = threadIdx.x >> 4;
    int c     = threadIdx.x & 15;
    int n     = blockIdx.x * NODES_PER_BLOCK + local;   // exact grid

    // cnt load issued first — overlaps the staging load below.
    int k = __ldg(cnt + n);

    // Stage first 32 slot indices of this node (one int2/thread, coalesced).
    // Entries beyond cnt[n] are stale-but-valid ids, never accumulated.
    {
        int2 v = __ldg(reinterpret_cast<const int2*>(slot + (size_t)n * CAP) + c);
        slot_sm[local][c * 2]     = v.x;
        slot_sm[local][c * 2 + 1] = v.y;
    }
    __syncwarp();   // producers == consumers' half-warp

    if (k > CAP) k = CAP;
    int kc = k < 32 ? k : 32;

    float4 acc = make_float4(0.f, 0.f, 0.f, 0.f);

    int j = 0;
    // 8-wide unroll: indices from smem (broadcast LDS), 8 independent 256B
    // row gathers in flight per group.
    for (; j + 8 <= kc; j += 8) {
        int s0 = slot_sm[local][j + 0];
        int s1 = slot_sm[local][j + 1];
        int s2 = slot_sm[local][j + 2];
        int s3 = slot_sm[local][j + 3];
        int s4 = slot_sm[local][j + 4];
        int s5 = slot_sm[local][j + 5];
        int s6 = slot_sm[local][j + 6];
        int s7 = slot_sm[local][j + 7];
        float4 v0 = __ldg(src4 + (size_t)s0 * 16 + c);
        float4 v1 = __ldg(src4 + (size_t)s1 * 16 + c);
        float4 v2 = __ldg(src4 + (size_t)s2 * 16 + c);
        float4 v3 = __ldg(src4 + (size_t)s3 * 16 + c);
        float4 v4 = __ldg(src4 + (size_t)s4 * 16 + c);
        float4 v5 = __ldg(src4 + (size_t)s5 * 16 + c);
        float4 v6 = __ldg(src4 + (size_t)s6 * 16 + c);
        float4 v7 = __ldg(src4 + (size_t)s7 * 16 + c);
        acc.x += (v0.x + v1.x) + (v2.x + v3.x) + ((v4.x + v5.x) + (v6.x + v7.x));
        acc.y += (v0.y + v1.y) + (v2.y + v3.y) + ((v4.y + v5.y) + (v6.y + v7.y));
        acc.z += (v0.z + v1.z) + (v2.z + v3.z) + ((v4.z + v5.z) + (v6.z + v7.z));
        acc.w += (v0.w + v1.w) + (v2.w + v3.w) + ((v4.w + v5.w) + (v6.w + v7.w));
    }
    if (j + 4 <= kc) {
        int s0 = slot_sm[local][j + 0];
        int s1 = slot_sm[local][j + 1];
        int s2 = slot_sm[local][j + 2];
        int s3 = slot_sm[local][j + 3];
        float4 v0 = __ldg(src4 + (size_t)s0 * 16 + c);
        float4 v1 = __ldg(src4 + (size_t)s1 * 16 + c);
        float4 v2 = __ldg(src4 + (size_t)s2 * 16 + c);
        float4 v3 = __ldg(src4 + (size_t)s3 * 16 + c);
        acc.x += (v0.x + v1.x) + (v2.x + v3.x);
        acc.y += (v0.y + v1.y) + (v2.y + v3.y);
        acc.z += (v0.z + v1.z) + (v2.z + v3.z);
        acc.w += (v0.w + v1.w) + (v2.w + v3.w);
        j += 4;
    }
    for (; j < kc; ++j) {
        int s = slot_sm[local][j];
        float4 v = __ldg(src4 + (size_t)s * 16 + c);
        acc.x += v.x; acc.y += v.y; acc.z += v.z; acc.w += v.w;
    }
    // Rare fallback: degree > 32 — global slot reads.
    for (j = 32; j < k; ++j) {
        int s = __ldg(slot + (size_t)n * CAP + j);
        float4 v = __ldg(src4 + (size_t)s * 16 + c);
        acc.x += v.x; acc.y += v.y; acc.z += v.z; acc.w += v.w;
    }

    *reinterpret_cast<float4*>(&S_sm[local][c * 4]) = acc;
    D_sm[local][c] = __ldg(dst4 + (size_t)n * 16 + c);
    __syncwarp();   // same half-warp produces and consumes S_sm/D_sm rows

    {
        int i  = c >> 1;
        int jh = c & 1;
        float4 o = make_float4(0.f, 0.f, 0.f, 0.f);
        #pragma unroll
        for (int p = 0; p < 8; ++p) {
            float  a = S_sm[local][i * 8 + p];
            float4 b = D_sm[local][p * 2 + jh];
            o.x = fmaf(a, b.x, o.x);
            o.y = fmaf(a, b.y, o.y);
            o.z = fmaf(a, b.z, o.z);
            o.w = fmaf(a, b.w, o.w);
        }
        const float inv = 0.3535533905932737622f;   // 1/sqrt(8)
        o.x *= inv; o.y *= inv; o.z *= inv; o.w *= inv;
        reinterpret_cast<float4*>(out + (size_t)n * FEAT)[c] = o;
    }
}

extern "C" void kernel_launch(void* const* d_in, const int* in_sizes, int n_in,
                              void* d_out, int out_size)
{
    const float* src_feat = (const float*)d_in[0];
    const float* dst_feat = (const float*)d_in[1];
    const int*   edge_src = (const int*)d_in[2];
    const int*   edge_dst = (const int*)d_in[3];
    float*       out      = (float*)d_out;

    void* cnt_ptr  = nullptr;
    void* slot_ptr = nullptr;
    cudaGetSymbolAddress(&cnt_ptr, g_cnt);
    cudaGetSymbolAddress(&slot_ptr, g_slot);

    cudaMemsetAsync(cnt_ptr, 0, (size_t)N_NODES * sizeof(int), 0);

    {
        int threads = 256;
        int work    = N_EDGES / 8;                 // 100000
        int blocks  = (work + threads - 1) / threads;
        build_buckets_kernel<<<blocks, threads>>>(
            reinterpret_cast<const int4*>(edge_src),
            reinterpret_cast<const int4*>(edge_dst),
            (int*)cnt_ptr, (int*)slot_ptr);
    }
    {
        int threads = NODES_PER_BLOCK * 16;        // 128
        int blocks  = N_NODES / NODES_PER_BLOCK;   // 6250 exact
        gather_matmul_kernel<<<blocks, threads>>>(
            reinterpret_cast<const float4*>(src_feat),
            reinterpret_cast<const float4*>(dst_feat),
            (const int*)cnt_ptr, (const int*)slot_ptr, out);
    }
}

// round 14
// speedup vs baseline: 1.1107x; 1.0616x over previous
#include <cuda_runtime.h>
#include <cuda_fp16.h>
#include <cuda_bf16.h>
#include <cstdint>

#define N_NODES 50000
#define N_EDGES 800000
#define FEAT    64
#define CAP     64   // Poisson(16): P(deg>=64) ~ 2e-18/node; 32<deg<=64 via fallback

__device__ int  g_cnt[N_NODES];
__device__ __half g_srch[(size_t)N_NODES * FEAT];   // fp16 copy of src_feat (6.4MB)
__device__ int  g_slot[(size_t)N_NODES * CAP];

// ---------------------------------------------------------------------------
// Pass 0: convert src_feat fp32 -> fp16 (one 19MB streaming pass).
// ---------------------------------------------------------------------------
__global__ void convert_src_kernel(const float4* __restrict__ src4,
                                   uint4*        __restrict__ dsth)
{
    int t = blockIdx.x * blockDim.x + threadIdx.x;
    if (t >= N_NODES * FEAT / 8) return;
    float4 a = __ldg(src4 + 2 * t);
    float4 b = __ldg(src4 + 2 * t + 1);
    __half2 h0 = __floats2half2_rn(a.x, a.y);
    __half2 h1 = __floats2half2_rn(a.z, a.w);
    __half2 h2 = __floats2half2_rn(b.x, b.y);
    __half2 h3 = __floats2half2_rn(b.z, b.w);
    uint4 o;
    o.x = *reinterpret_cast<unsigned*>(&h0);
    o.y = *reinterpret_cast<unsigned*>(&h1);
    o.z = *reinterpret_cast<unsigned*>(&h2);
    o.w = *reinterpret_cast<unsigned*>(&h3);
    dsth[t] = o;
}

// ---------------------------------------------------------------------------
// Pass 1: bucket build. One thread per 8 edges (2x int4 loads).
// ---------------------------------------------------------------------------
__global__ void build_buckets_kernel(const int4* __restrict__ es4,
                                     const int4* __restrict__ ed4,
                                     int*        __restrict__ cnt,
                                     int*        __restrict__ slot)
{
    int t = blockIdx.x * blockDim.x + threadIdx.x;
    if (t >= N_EDGES / 8) return;
    int4 s0 = __ldg(es4 + 2 * t);
    int4 s1 = __ldg(es4 + 2 * t + 1);
    int4 d0 = __ldg(ed4 + 2 * t);
    int4 d1 = __ldg(ed4 + 2 * t + 1);
    int p;
    p = atomicAdd(cnt + d0.x, 1); if (p < CAP) slot[(size_t)d0.x * CAP + p] = s0.x;
    p = atomicAdd(cnt + d0.y, 1); if (p < CAP) slot[(size_t)d0.y * CAP + p] = s0.y;
    p = atomicAdd(cnt + d0.z, 1); if (p < CAP) slot[(size_t)d0.z * CAP + p] = s0.z;
    p = atomicAdd(cnt + d0.w, 1); if (p < CAP) slot[(size_t)d0.w * CAP + p] = s0.w;
    p = atomicAdd(cnt + d1.x, 1); if (p < CAP) slot[(size_t)d1.x * CAP + p] = s1.x;
    p = atomicAdd(cnt + d1.y, 1); if (p < CAP) slot[(size_t)d1.y * CAP + p] = s1.y;
    p = atomicAdd(cnt + d1.z, 1); if (p < CAP) slot[(size_t)d1.z * CAP + p] = s1.z;
    p = atomicAdd(cnt + d1.w, 1); if (p < CAP) slot[(size_t)d1.w * CAP + p] = s1.w;
}

// ---------------------------------------------------------------------------
// Pass 2 (fused): R13 structure; src rows now fp16 (uint2 per thread per row,
// half the L2/L1 traffic, half the in-flight register footprint). Accumulate
// in fp32. 16 threads/node, 128-thread blocks, warp-local sync.
// ---------------------------------------------------------------------------
#define NODES_PER_BLOCK 8   // 128 threads; 50000/8 = 6250 exact blocks

__device__ __forceinline__ void hacc(float4& acc, uint2 u) {
    __half2 h0 = *reinterpret_cast<__half2*>(&u.x);
    __half2 h1 = *reinterpret_cast<__half2*>(&u.y);
    float2 f0 = __half22float2(h0);
    float2 f1 = __half22float2(h1);
    acc.x += f0.x; acc.y += f0.y; acc.z += f1.x; acc.w += f1.y;
}

__global__ void
gather_matmul_kernel(const uint2*  __restrict__ srch,   // fp16 rows, 16B/thread-chunk
                     const float4* __restrict__ dst4,
                     const int*    __restrict__ cnt,
                     const int*    __restrict__ slot,
                     float*        __restrict__ out)
{
    __shared__ float  S_sm[NODES_PER_BLOCK][68];     // padded rows
    __shared__ float4 D_sm[NODES_PER_BLOCK][18];
    __shared__ int    slot_sm[NODES_PER_BLOCK][33];  // 32 idx + pad

    int local = threadIdx.x >> 4;
    int c     = threadIdx.x & 15;
    int n     = blockIdx.x * NODES_PER_BLOCK + local;   // exact grid

    int k = __ldg(cnt + n);   // overlaps staging load

    {
        int2 v = __ldg(reinterpret_cast<const int2*>(slot + (size_t)n * CAP) + c);
        slot_sm[local][c * 2]     = v.x;
        slot_sm[local][c * 2 + 1] = v.y;
    }
    __syncwarp();

    if (k > CAP) k = CAP;
    int kc = k < 32 ? k : 32;

    float4 acc = make_float4(0.f, 0.f, 0.f, 0.f);

    int j = 0;
    for (; j + 8 <= kc; j += 8) {
        int s0 = slot_sm[local][j + 0];
        int s1 = slot_sm[local][j + 1];
        int s2 = slot_sm[local][j + 2];
        int s3 = slot_sm[local][j + 3];
        int s4 = slot_sm[local][j + 4];
        int s5 = slot_sm[local][j + 5];
        int s6 = slot_sm[local][j + 6];
        int s7 = slot_sm[local][j + 7];
        uint2 u0 = __ldg(srch + (size_t)s0 * 16 + c);
        uint2 u1 = __ldg(srch + (size_t)s1 * 16 + c);
        uint2 u2 = __ldg(srch + (size_t)s2 * 16 + c);
        uint2 u3 = __ldg(srch + (size_t)s3 * 16 + c);
        uint2 u4 = __ldg(srch + (size_t)s4 * 16 + c);
        uint2 u5 = __ldg(srch + (size_t)s5 * 16 + c);
        uint2 u6 = __ldg(srch + (size_t)s6 * 16 + c);
        uint2 u7 = __ldg(srch + (size_t)s7 * 16 + c);
        hacc(acc, u0); hacc(acc, u1); hacc(acc, u2); hacc(acc, u3);
        hacc(acc, u4); hacc(acc, u5); hacc(acc, u6); hacc(acc, u7);
    }
    if (j + 4 <= kc) {
        int s0 = slot_sm[local][j + 0];
        int s1 = slot_sm[local][j + 1];
        int s2 = slot_sm[local][j + 2];
        int s3 = slot_sm[local][j + 3];
        uint2 u0 = __ldg(srch + (size_t)s0 * 16 + c);
        uint2 u1 = __ldg(srch + (size_t)s1 * 16 + c);
        uint2 u2 = __ldg(srch + (size_t)s2 * 16 + c);
        uint2 u3 = __ldg(srch + (size_t)s3 * 16 + c);
        hacc(acc, u0); hacc(acc, u1); hacc(acc, u2); hacc(acc, u3);
        j += 4;
    }
    for (; j < kc; ++j) {
        int s = slot_sm[local][j];
        uint2 u = __ldg(srch + (size_t)s * 16 + c);
        hacc(acc, u);
    }
    // Rare fallback: degree > 32 — global slot reads.
    for (j = 32; j < k; ++j) {
        int s = __ldg(slot + (size_t)n * CAP + j);
        uint2 u = __ldg(srch + (size_t)s * 16 + c);
        hacc(acc, u);
    }

    *reinterpret_cast<float4*>(&S_sm[local][c * 4]) = acc;
    D_sm[local][c] = __ldg(dst4 + (size_t)n * 16 + c);
    __syncwarp();

    {
        int i  = c >> 1;
        int jh = c & 1;
        float4 o = make_float4(0.f, 0.f, 0.f, 0.f);
        #pragma unroll
        for (int p = 0; p < 8; ++p) {
            float  a = S_sm[local][i * 8 + p];
            float4 b = D_sm[local][p * 2 + jh];
            o.x = fmaf(a, b.x, o.x);
            o.y = fmaf(a, b.y, o.y);
            o.z = fmaf(a, b.z, o.z);
            o.w = fmaf(a, b.w, o.w);
        }
        const float inv = 0.3535533905932737622f;   // 1/sqrt(8)
        o.x *= inv; o.y *= inv; o.z *= inv; o.w *= inv;
        reinterpret_cast<float4*>(out + (size_t)n * FEAT)[c] = o;
    }
}

extern "C" void kernel_launch(void* const* d_in, const int* in_sizes, int n_in,
                              void* d_out, int out_size)
{
    const float* src_feat = (const float*)d_in[0];
    const float* dst_feat = (const float*)d_in[1];
    const int*   edge_src = (const int*)d_in[2];
    const int*   edge_dst = (const int*)d_in[3];
    float*       out      = (float*)d_out;

    void* cnt_ptr  = nullptr;
    void* slot_ptr = nullptr;
    void* srch_ptr = nullptr;
    cudaGetSymbolAddress(&cnt_ptr, g_cnt);
    cudaGetSymbolAddress(&slot_ptr, g_slot);
    cudaGetSymbolAddress(&srch_ptr, g_srch);

    cudaMemsetAsync(cnt_ptr, 0, (size_t)N_NODES * sizeof(int), 0);

    {   // Pass 0: fp32 -> fp16 src copy (runs concurrently with build's stream order)
        int threads = 256;
        int work    = N_NODES * FEAT / 8;          // 400000
        int blocks  = (work + threads - 1) / threads;
        convert_src_kernel<<<blocks, threads>>>(
            reinterpret_cast<const float4*>(src_feat),
            reinterpret_cast<uint4*>(srch_ptr));
    }
    {
        int threads = 256;
        int work    = N_EDGES / 8;                 // 100000
        int blocks  = (work + threads - 1) / threads;
        build_buckets_kernel<<<blocks, threads>>>(
            reinterpret_cast<const int4*>(edge_src),
            reinterpret_cast<const int4*>(edge_dst),
            (int*)cnt_ptr, (int*)slot_ptr);
    }
    {
        int threads = NODES_PER_BLOCK * 16;        // 128
        int blocks  = N_NODES / NODES_PER_BLOCK;   // 6250 exact
        gather_matmul_kernel<<<blocks, threads>>>(
            reinterpret_cast<const uint2*>(srch_ptr),
            reinterpret_cast<const float4*>(dst_feat),
            (const int*)cnt_ptr, (const int*)slot_ptr, out);
    }
}